// round 4
// baseline (speedup 1.0000x reference)
#include <cuda_runtime.h>

#define TT 512
#define BB 32
#define HH 512

// h double buffer: [dir][parity][b*H + j]   (read by all blocks of a direction)
__device__ float g_h[2][2][BB * HH];
// c state, transposed layout for coalesced access: [dir][j*B + b] (private to owner warp)
__device__ float g_c[2][HH * BB];

typedef unsigned long long ull;

static __device__ __forceinline__ ull pk(float x, float y) {
    ull r; asm("mov.b64 %0,{%1,%2};" : "=l"(r) : "f"(x), "f"(y)); return r;
}
static __device__ __forceinline__ void up(ull v, float& x, float& y) {
    asm("mov.b64 {%0,%1},%2;" : "=f"(x), "=f"(y) : "l"(v));
}
static __device__ __forceinline__ ull fma2(ull a, ull b, ull c) {
    ull d; asm("fma.rn.f32x2 %0,%1,%2,%3;" : "=l"(d) : "l"(a), "l"(b), "l"(c)); return d;
}
static __device__ __forceinline__ ull add2(ull a, ull b) {
    ull d; asm("add.rn.f32x2 %0,%1,%2;" : "=l"(d) : "l"(a), "l"(b)); return d;
}
static __device__ __forceinline__ float sigm(float x) {
    return __fdividef(1.f, 1.f + __expf(-x));
}
static __device__ __forceinline__ float tanh_(float x) {
    float a = fabsf(x), e = __expf(-2.f * a);
    return copysignf(__fdividef(1.f - e, 1.f + e), x);
}

// ---------------- embedding gather: out_emb[T][B][H] = emb[seq] ----------------
__global__ void embed_kernel(const int* __restrict__ seq,
                             const float* __restrict__ emb,
                             float* __restrict__ out_emb)
{
    int gw = blockIdx.x * 8 + (threadIdx.x >> 5);
    int lane = threadIdx.x & 31;
    const float4* ev = (const float4*)emb;
    float4* dv = (float4*)out_emb;
    for (int n = gw; n < TT * BB; n += gridDim.x * 8) {
        int tok = __ldg(seq + n);
        const float4* s = ev + (size_t)tok * (HH / 4);
        float4* d = dv + (size_t)n * (HH / 4);
#pragma unroll
        for (int i = 0; i < 4; i++) d[lane + i * 32] = __ldg(s + lane + i * 32);
    }
}

// ---------------- init: zero h parity-0 and c for both directions ----------------
__global__ void init_kernel()
{
    int i = blockIdx.x * blockDim.x + threadIdx.x;   // 0 .. B*H-1  (grid 64x256)
    g_h[0][0][i] = 0.f;
    g_h[1][0][i] = 0.f;
    g_c[0][i] = 0.f;
    g_c[1][i] = 0.f;
}

// ---------------- one LSTM step, both directions (grid = 128 blocks) ----------------
extern __shared__ float h_sm[];   // BB*HH floats = 64KB

__global__ void __launch_bounds__(256, 1) step_kernel(
    int t,
    const float* __restrict__ x,        // out_emb [T][B][H]
    const int* __restrict__ lens,
    const float* __restrict__ Wih_f, const float* __restrict__ Whh_f,
    const float* __restrict__ bih_f, const float* __restrict__ bhh_f,
    const float* __restrict__ Wih_b, const float* __restrict__ Whh_b,
    const float* __restrict__ bih_b, const float* __restrict__ bhh_b,
    float* __restrict__ out)
{
    const int bid = blockIdx.x, tid = threadIdx.x;
    const int w = tid >> 5, lane = tid & 31;
    const int dir = bid >> 6;
    const int j0 = (bid & 63) * 8;
    const int j = j0 + w;                        // this warp's hidden unit
    const int tt = dir ? (TT - 1 - t) : t;       // logical time index

    float* out_outputs = out;                             // [T][B][2][H]
    float* out_hidden  = out + (size_t)TT * BB * 2 * HH;  // [2][T][B][H]

    const float* Wih = dir ? Wih_b : Wih_f;
    const float* Whh = dir ? Whh_b : Whh_f;
    const float* bih = dir ? bih_b : bih_f;
    const float* bhh = dir ? bhh_b : bhh_f;

    const float* hcur = g_h[dir][t & 1];
    float* hnxt = g_h[dir][(t & 1) ^ 1];

    // stage h[32][512] into SMEM (L1 flushed at launch boundary -> plain loads safe)
    {
        const float4* s = (const float4*)hcur;
        float4* d = (float4*)h_sm;
#pragma unroll
        for (int i = 0; i < 16; i++) d[tid + i * 256] = s[tid + i * 256];
    }

    // load this warp's weight slice into registers (L2-resident after step 0)
    // chunks q=0..3: Wih k-range (q*128), q=4..7: Whh; 4 consecutive k per lane
    ull w01[32], w23[32];
#pragma unroll
    for (int q = 0; q < 8; q++) {
        const float* Ws = (q < 4) ? Wih : Whh;
        const int kb = (q & 3) * 128 + lane * 4;
        float4 vi = *(const float4*)(Ws + (size_t)j * HH + kb);
        float4 vf = *(const float4*)(Ws + (size_t)(HH + j) * HH + kb);
        float4 vg = *(const float4*)(Ws + (size_t)(2 * HH + j) * HH + kb);
        float4 vo = *(const float4*)(Ws + (size_t)(3 * HH + j) * HH + kb);
        w01[q * 4 + 0] = pk(vi.x, vf.x); w23[q * 4 + 0] = pk(vg.x, vo.x);
        w01[q * 4 + 1] = pk(vi.y, vf.y); w23[q * 4 + 1] = pk(vg.y, vo.y);
        w01[q * 4 + 2] = pk(vi.z, vf.z); w23[q * 4 + 2] = pk(vg.z, vo.z);
        w01[q * 4 + 3] = pk(vi.w, vf.w); w23[q * 4 + 3] = pk(vg.w, vo.w);
    }

    const float bi = bih[j] + bhh[j];
    const float bf = bih[HH + j] + bhh[HH + j];
    const float bg = bih[2 * HH + j] + bhh[2 * HH + j];
    const float bo = bih[3 * HH + j] + bhh[3 * HH + j];

    __syncthreads();   // h_sm ready

    float gi = 0.f, gf = 0.f, gg = 0.f, go = 0.f;
#pragma unroll 1
    for (int b = 0; b < BB; b++) {
        const float4* xs = (const float4*)x + ((size_t)tt * BB + b) * (HH / 4) + lane;
        const float4* hs = (const float4*)h_sm + b * (HH / 4) + lane;
        ull a0 = 0, a1 = 0, a2 = 0, a3 = 0;
#pragma unroll
        for (int q = 0; q < 4; q++) {            // x @ Wih^T
            float4 v = __ldg(xs + q * 32);
            ull d0 = pk(v.x, v.x), d1 = pk(v.y, v.y), d2 = pk(v.z, v.z), d3 = pk(v.w, v.w);
            a0 = fma2(w01[q * 4 + 0], d0, a0); a2 = fma2(w23[q * 4 + 0], d0, a2);
            a1 = fma2(w01[q * 4 + 1], d1, a1); a3 = fma2(w23[q * 4 + 1], d1, a3);
            a0 = fma2(w01[q * 4 + 2], d2, a0); a2 = fma2(w23[q * 4 + 2], d2, a2);
            a1 = fma2(w01[q * 4 + 3], d3, a1); a3 = fma2(w23[q * 4 + 3], d3, a3);
        }
#pragma unroll
        for (int q = 0; q < 4; q++) {            // h @ Whh^T
            float4 v = hs[q * 32];
            ull d0 = pk(v.x, v.x), d1 = pk(v.y, v.y), d2 = pk(v.z, v.z), d3 = pk(v.w, v.w);
            a0 = fma2(w01[(q + 4) * 4 + 0], d0, a0); a2 = fma2(w23[(q + 4) * 4 + 0], d0, a2);
            a1 = fma2(w01[(q + 4) * 4 + 1], d1, a1); a3 = fma2(w23[(q + 4) * 4 + 1], d1, a3);
            a0 = fma2(w01[(q + 4) * 4 + 2], d2, a0); a2 = fma2(w23[(q + 4) * 4 + 2], d2, a2);
            a1 = fma2(w01[(q + 4) * 4 + 3], d3, a1); a3 = fma2(w23[(q + 4) * 4 + 3], d3, a3);
        }
        ull a01 = add2(a0, a1), a23 = add2(a2, a3);
#pragma unroll
        for (int s = 16; s; s >>= 1) {
            a01 = add2(a01, __shfl_xor_sync(0xffffffffu, a01, s));
            a23 = add2(a23, __shfl_xor_sync(0xffffffffu, a23, s));
        }
        if (lane == b) { up(a01, gi, gf); up(a23, gg, go); }
    }

    // lane b holds batch b's gate sums for unit j
    float h_prev = h_sm[lane * HH + j];                 // one-time 32-way-conflict load
    float c_prev = g_c[dir][j * BB + lane];             // coalesced (transposed layout)

    float iv = sigm(gi + bi), fv = sigm(gf + bf);
    float gv = tanh_(gg + bg), ov = sigm(go + bo);
    float cn = fv * c_prev + iv * gv;
    float hn = ov * tanh_(cn);
    const bool m = (tt < __ldg(lens + lane));
    float h_keep = m ? hn : h_prev;
    float c_keep = m ? cn : c_prev;
    float oz = m ? hn : 0.f;

    g_c[dir][j * BB + lane] = c_keep;                   // coalesced

    __shared__ float hb_h[8][33], hb_o[8][33];
    hb_h[w][lane] = h_keep;
    hb_o[w][lane] = oz;
    __syncthreads();

    // transposed epilogue: thread -> (b = tid>>3, jl = tid&7); 8 consecutive j = 32B stores
    {
        int b = tid >> 3, jl = tid & 7, jj = j0 + jl;
        float hs_ = hb_h[jl][b], os_ = hb_o[jl][b];
        hnxt[b * HH + jj] = hs_;
        out_outputs[((size_t)(tt * BB + b) * 2 + dir) * HH + jj] = os_;
        out_hidden[((size_t)(dir * TT + tt) * BB + b) * HH + jj] = os_;
    }
}

extern "C" void kernel_launch(void* const* d_in, const int* in_sizes, int n_in,
                              void* d_out, int out_size) {
    (void)in_sizes; (void)n_in; (void)out_size;
    const int*   seq   = (const int*)d_in[0];
    const int*   lens  = (const int*)d_in[1];
    const float* emb   = (const float*)d_in[2];
    const float* Wih_f = (const float*)d_in[3];
    const float* Whh_f = (const float*)d_in[4];
    const float* bih_f = (const float*)d_in[5];
    const float* bhh_f = (const float*)d_in[6];
    const float* Wih_b = (const float*)d_in[7];
    const float* Whh_b = (const float*)d_in[8];
    const float* bih_b = (const float*)d_in[9];
    const float* bhh_b = (const float*)d_in[10];
    float* out = (float*)d_out;
    float* out_emb = out + (size_t)4 * TT * BB * HH;    // [T][B][H]

    static int smem_set = 0;
    if (!smem_set) {
        cudaFuncSetAttribute(step_kernel, cudaFuncAttributeMaxDynamicSharedMemorySize,
                             BB * HH * (int)sizeof(float));
        smem_set = 1;
    }

    embed_kernel<<<128, 256>>>(seq, emb, out_emb);      // also produces x for the scan
    init_kernel<<<64, 256>>>();
    for (int t = 0; t < TT; t++)
        step_kernel<<<128, 256, BB * HH * sizeof(float)>>>(
            t, out_emb, lens,
            Wih_f, Whh_f, bih_f, bhh_f,
            Wih_b, Whh_b, bih_b, bhh_b, out);
}

// round 5
// speedup vs baseline: 1.3588x; 1.3588x over previous
#include <cuda_runtime.h>

#define TT 512
#define BB 32
#define HH 512
#define NREC 128          // barrier-participating blocks (2 dirs x 64)
#define NEMB 12           // embedding-copy blocks (no barrier)

__device__ float g_h[2][2][BB * HH];      // [dir][parity][b*H+j]
__device__ unsigned int g_flags[NREC];    // monotonic barrier flags (persist across replays)
__device__ unsigned int g_dead;           // poison: set if a barrier ever times out

typedef unsigned long long ull;

static __device__ __forceinline__ ull pk(float x, float y) {
    ull r; asm("mov.b64 %0,{%1,%2};" : "=l"(r) : "f"(x), "f"(y)); return r;
}
static __device__ __forceinline__ void up(ull v, float& x, float& y) {
    asm("mov.b64 {%0,%1},%2;" : "=f"(x), "=f"(y) : "l"(v));
}
static __device__ __forceinline__ ull fma2(ull a, ull b, ull c) {
    ull d; asm("fma.rn.f32x2 %0,%1,%2,%3;" : "=l"(d) : "l"(a), "l"(b), "l"(c)); return d;
}
static __device__ __forceinline__ ull add2(ull a, ull b) {
    ull d; asm("add.rn.f32x2 %0,%1,%2;" : "=l"(d) : "l"(a), "l"(b)); return d;
}
static __device__ __forceinline__ float sigm(float x) {
    return __fdividef(1.f, 1.f + __expf(-x));
}
static __device__ __forceinline__ float tanh_(float x) {
    float a = fabsf(x), e = __expf(-2.f * a);
    return copysignf(__fdividef(1.f - e, 1.f + e), x);
}

// 8 packed FMAs: v broadcast over 4 k, into (i,f) and (g,o) accumulator pairs
static __device__ __forceinline__ void mac4(const ull* W01, const ull* W23, int q4, float4 v,
                                            ull& a0, ull& a1, ull& a2, ull& a3) {
    ull d0 = pk(v.x, v.x), d1 = pk(v.y, v.y), d2 = pk(v.z, v.z), d3 = pk(v.w, v.w);
    a0 = fma2(W01[q4 + 0], d0, a0); a2 = fma2(W23[q4 + 0], d0, a2);
    a1 = fma2(W01[q4 + 1], d1, a1); a3 = fma2(W23[q4 + 1], d1, a3);
    a0 = fma2(W01[q4 + 2], d2, a0); a2 = fma2(W23[q4 + 2], d2, a2);
    a1 = fma2(W01[q4 + 3], d3, a1); a3 = fma2(W23[q4 + 3], d3, a3);
}

// per-direction barrier among 64 blocks; monotonic, wrap-safe, timeout-poisoned
static __device__ __forceinline__ void gbar(int dir, int bid, unsigned int tgt) {
    __threadfence();
    __syncthreads();
    if (threadIdx.x < 32) {
        if (threadIdx.x == 0) atomicExch(&g_flags[bid], tgt);
        volatile unsigned int* f = g_flags + dir * 64;
        volatile unsigned int* dead = &g_dead;
        unsigned int it = 0;
        bool ok;
        do {
            unsigned int a = f[threadIdx.x], b = f[threadIdx.x + 32];
            ok = ((int)(a - tgt) >= 0) && ((int)(b - tgt) >= 0);
            if (++it > (1u << 18)) {                 // ~60ms: never in a healthy run
                if (threadIdx.x == 0) atomicExch(&g_dead, 1u);
                break;
            }
        } while (!__all_sync(0xffffffffu, ok) && *dead == 0u);
        __threadfence();
    }
    __syncthreads();
}

extern __shared__ float h_sm[];               // BB*HH floats = 64KB

__global__ void __launch_bounds__(256, 1) bilstm_kernel(
    const int* __restrict__ seq, const int* __restrict__ lens,
    const float* __restrict__ emb,
    const float* __restrict__ Wih_f, const float* __restrict__ Whh_f,
    const float* __restrict__ bih_f, const float* __restrict__ bhh_f,
    const float* __restrict__ Wih_b, const float* __restrict__ Whh_b,
    const float* __restrict__ bih_b, const float* __restrict__ bhh_b,
    float* __restrict__ out)
{
    const int bid = blockIdx.x, tid = threadIdx.x;
    const int w = tid >> 5, lane = tid & 31;

    float* out_outputs = out;                             // [T][B][2][H]
    float* out_hidden  = out + (size_t)TT * BB * 2 * HH;  // [2][T][B][H]
    float* out_emb     = out + (size_t)4 * TT * BB * HH;  // [T][B][H]

    if (bid >= NREC) {                                    // embedding copy blocks
        int gw = (bid - NREC) * 8 + w;
        const float4* ev = (const float4*)emb;
        float4* dv = (float4*)out_emb;
        for (int n = gw; n < TT * BB; n += NEMB * 8) {
            int tok = __ldg(seq + n);
            const float4* s = ev + (size_t)tok * (HH / 4);
            float4* d = dv + (size_t)n * (HH / 4);
#pragma unroll
            for (int i = 0; i < 4; i++) d[lane + i * 32] = __ldg(s + lane + i * 32);
        }
        return;
    }

    const int dir = bid >> 6;
    const int j0 = (bid & 63) * 8;
    const int j = j0 + w;                                 // this warp's hidden unit

    const float* Wih = dir ? Wih_b : Wih_f;
    const float* Whh = dir ? Whh_b : Whh_f;
    const float* bih = dir ? bih_b : bih_f;
    const float* bhh = dir ? bhh_b : bhh_f;

    const float bi = bih[j] + bhh[j];
    const float bf = bih[HH + j] + bhh[HH + j];
    const float bg = bih[2 * HH + j] + bhh[2 * HH + j];
    const float bo = bih[3 * HH + j] + bhh[3 * HH + j];

    // persistent weights: chunks q=0..3 Wih, q=4..7 Whh; lane covers 4 consecutive k per chunk
    ull w01[32], w23[32];
#pragma unroll
    for (int q = 0; q < 8; q++) {
        const float* Ws = (q < 4) ? Wih : Whh;
        const int kb = (q & 3) * 128 + lane * 4;
        float4 vi = *(const float4*)(Ws + (size_t)j * HH + kb);
        float4 vf = *(const float4*)(Ws + (size_t)(HH + j) * HH + kb);
        float4 vg = *(const float4*)(Ws + (size_t)(2 * HH + j) * HH + kb);
        float4 vo = *(const float4*)(Ws + (size_t)(3 * HH + j) * HH + kb);
        w01[q * 4 + 0] = pk(vi.x, vf.x); w23[q * 4 + 0] = pk(vg.x, vo.x);
        w01[q * 4 + 1] = pk(vi.y, vf.y); w23[q * 4 + 1] = pk(vg.y, vo.y);
        w01[q * 4 + 2] = pk(vi.z, vf.z); w23[q * 4 + 2] = pk(vg.z, vo.z);
        w01[q * 4 + 3] = pk(vi.w, vf.w); w23[q * 4 + 3] = pk(vg.w, vo.w);
    }

    __shared__ float hb_h[8][33], hb_o[8][33];

    // zero initial h (parity 0): thread -> (b = tid>>3, jl = tid&7)
    {
        int b = tid >> 3, jl = tid & 7;
        __stcg(&g_h[dir][0][b * HH + j0 + jl], 0.f);
    }

    float c_state = 0.f, h_state = 0.f;                   // lane = batch index
    const int mylen = __ldg(lens + lane);
    unsigned int tgt = g_flags[bid];
    gbar(dir, bid, ++tgt);                                // zeros visible everywhere

    for (int t = 0; t < TT; t++) {
        const int tt = dir ? (TT - 1 - t) : t;
        const float* hcur = g_h[dir][t & 1];
        float* hnxt = g_h[dir][(t & 1) ^ 1];

        // stage h[32][512] to SMEM, MUST bypass L1 (written by other SMs, L1 persists here)
        {
            const float4* s = (const float4*)hcur;
            float4* d = (float4*)h_sm;
#pragma unroll
            for (int i = 0; i < 16; i++) d[tid + i * 256] = __ldcg(s + tid + i * 256);
        }
        __syncthreads();

        const int tok_reg = __ldg(seq + tt * BB + lane);

        float gi = 0.f, gf = 0.f, gg = 0.f, go = 0.f;
#pragma unroll 1
        for (int b = 0; b < BB; b += 2) {                 // 2 batches in flight
            const int tok0 = __shfl_sync(0xffffffffu, tok_reg, b);
            const int tok1 = __shfl_sync(0xffffffffu, tok_reg, b + 1);
            const float4* xs0 = (const float4*)emb + (size_t)tok0 * (HH / 4) + lane;
            const float4* xs1 = (const float4*)emb + (size_t)tok1 * (HH / 4) + lane;
            const float4* hs0 = (const float4*)h_sm + b * (HH / 4) + lane;
            const float4* hs1 = hs0 + (HH / 4);
            ull p0 = 0, p1 = 0, p2 = 0, p3 = 0;
            ull r0 = 0, r1 = 0, r2 = 0, r3 = 0;
#pragma unroll
            for (int q = 0; q < 4; q++) {                 // x @ Wih^T
                mac4(w01, w23, q * 4, __ldg(xs0 + q * 32), p0, p1, p2, p3);
                mac4(w01, w23, q * 4, __ldg(xs1 + q * 32), r0, r1, r2, r3);
            }
#pragma unroll
            for (int q = 0; q < 4; q++) {                 // h @ Whh^T
                mac4(w01, w23, (q + 4) * 4, hs0[q * 32], p0, p1, p2, p3);
                mac4(w01, w23, (q + 4) * 4, hs1[q * 32], r0, r1, r2, r3);
            }
            ull A = add2(p0, p1), Bc = add2(p2, p3);
            ull C = add2(r0, r1), D = add2(r2, r3);
#pragma unroll
            for (int s = 16; s; s >>= 1) {                // 4 chains interleaved
                A  = add2(A,  __shfl_xor_sync(0xffffffffu, A,  s));
                Bc = add2(Bc, __shfl_xor_sync(0xffffffffu, Bc, s));
                C  = add2(C,  __shfl_xor_sync(0xffffffffu, C,  s));
                D  = add2(D,  __shfl_xor_sync(0xffffffffu, D,  s));
            }
            if (lane == b)     { up(A, gi, gf); up(Bc, gg, go); }
            if (lane == b + 1) { up(C, gi, gf); up(D,  gg, go); }
        }

        // lane b holds batch b's gate sums for unit j
        float iv = sigm(gi + bi), fv = sigm(gf + bf);
        float gv = tanh_(gg + bg), ov = sigm(go + bo);
        float cn = fv * c_state + iv * gv;
        float hn = ov * tanh_(cn);
        const bool m = (tt < mylen);
        h_state = m ? hn : h_state;
        c_state = m ? cn : c_state;
        float oz = m ? hn : 0.f;

        hb_h[w][lane] = h_state;
        hb_o[w][lane] = oz;
        __syncthreads();

        // transposed epilogue: thread -> (b, jl); 8 consecutive j = 32B per store
        {
            int b = tid >> 3, jl = tid & 7, jj = j0 + jl;
            float hs_ = hb_h[jl][b], os_ = hb_o[jl][b];
            __stcg(&hnxt[b * HH + jj], hs_);
            out_outputs[((size_t)(tt * BB + b) * 2 + dir) * HH + jj] = os_;
            out_hidden[((size_t)(dir * TT + tt) * BB + b) * HH + jj] = os_;
        }

        gbar(dir, bid, ++tgt);
    }
}

extern "C" void kernel_launch(void* const* d_in, const int* in_sizes, int n_in,
                              void* d_out, int out_size) {
    (void)in_sizes; (void)n_in; (void)out_size;
    static int smem_set = 0;
    if (!smem_set) {
        cudaFuncSetAttribute(bilstm_kernel, cudaFuncAttributeMaxDynamicSharedMemorySize,
                             BB * HH * (int)sizeof(float));
        smem_set = 1;
    }
    bilstm_kernel<<<NREC + NEMB, 256, BB * HH * sizeof(float)>>>(
        (const int*)d_in[0], (const int*)d_in[1], (const float*)d_in[2],
        (const float*)d_in[3], (const float*)d_in[4], (const float*)d_in[5], (const float*)d_in[6],
        (const float*)d_in[7], (const float*)d_in[8], (const float*)d_in[9], (const float*)d_in[10],
        (float*)d_out);
}